// round 9
// baseline (speedup 1.0000x reference)
#include <cuda_runtime.h>
#include <cuda_bf16.h>

// ---------------------------------------------------------------------------
// Problem constants
// ---------------------------------------------------------------------------
constexpr long NV0 = 300000, NV1 = 98304, NV2 = 12288, NV3 = 1536, NV4 = 192;
constexpr long NE0 = 3600000, NE1 = 786432, NE2 = 196608, NE3 = 24576, NE4 = 3072;
constexpr long TOTV = NV0 + NV1 + NV2 + NV3 + NV4;
constexpr long TOTE = NE0 + NE1 + NE2 + NE3 + NE4;

// ---------------------------------------------------------------------------
// Float scratch. Feature rows carry pos: [feats C, px, py, pz] = C+3 wide.
// ---------------------------------------------------------------------------
constexpr long O_FC1 = 0;                      // [NV1, 19]
constexpr long O_FC2 = O_FC1 + NV1 * 19;       // [NV2, 67]
constexpr long O_FC3 = O_FC2 + NV2 * 67;       // [NV3, 131]
constexpr long O_FC4 = O_FC3 + NV3 * 131;      // [NV4, 131]
constexpr long O_P1P = O_FC4 + NV4 * 131;
constexpr long O_P2P = O_P1P + NV1 * 3;
constexpr long O_P3P = O_P2P + NV2 * 3;
constexpr long O_P4P = O_P3P + NV3 * 3;
constexpr long O_CNT1 = O_P4P + NV4 * 3;
constexpr long O_CNT2 = O_CNT1 + NV1;
constexpr long O_CNT3 = O_CNT2 + NV2;
constexpr long O_CNT4 = O_CNT3 + NV3;
constexpr long ZERO_N0 = O_CNT4 + NV4;
constexpr long ZERO_N = (ZERO_N0 + 3) & ~3L;
constexpr long O_PXA = ZERO_N;                 // [NV0] float4
constexpr long TOTAL_N = O_PXA + NV0 * 4;

__device__ __align__(16) float g_buf[TOTAL_N];

// Int scratch: concatenated CSR over all 5 layers.
constexpr long I_CNT = 0;
constexpr long I_ROW = I_CNT + TOTV;
constexpr long I_CUR = I_ROW + TOTV;
constexpr long I_EBIN = I_CUR + TOTV;
constexpr long I_BS  = I_EBIN + TOTE;
constexpr long I_BO  = I_BS + 2048;
constexpr long TOTAL_I = I_BO + 2048;

__device__ __align__(16) int g_csr[TOTAL_I];

constexpr int VOFF0 = 0;
constexpr int VOFF1 = (int)NV0;
constexpr int VOFF2 = (int)(NV0 + NV1);
constexpr int VOFF3 = (int)(NV0 + NV1 + NV2);
constexpr int VOFF4 = (int)(NV0 + NV1 + NV2 + NV3);

struct Batch5 {
    const int* e[5];
    long E[5];
    int voff[5];
};

// ---------------------------------------------------------------------------
// f32x2 packed helpers (Blackwell FFMA2; exact fp32 semantics)
// ---------------------------------------------------------------------------
typedef unsigned long long u64;
__device__ __forceinline__ u64 pk2(float v) {
    u64 r;
    asm("mov.b64 %0, {%1, %1};" : "=l"(r) : "r"(__float_as_uint(v)));
    return r;
}
__device__ __forceinline__ float2 up2(u64 v) {
    unsigned lo, hi;
    asm("mov.b64 {%0, %1}, %2;" : "=r"(lo), "=r"(hi) : "l"(v));
    return make_float2(__uint_as_float(lo), __uint_as_float(hi));
}
#define FMA2(acc, a, b) \
    asm("fma.rn.f32x2 %0, %1, %2, %3;" : "=l"(acc) : "l"(a), "l"(b), "l"(acc))

// ---------------------------------------------------------------------------
// init: zero float region, zero CSR counts, build pxa = (pos, x)
// ---------------------------------------------------------------------------
__global__ void init_kernel(float* __restrict__ buf, int* __restrict__ cnt,
                            const float* __restrict__ pos, const float* __restrict__ x) {
    long t = (long)blockIdx.x * blockDim.x + threadIdx.x;
    long T = (long)gridDim.x * blockDim.x;
    float4 z = make_float4(0.f, 0.f, 0.f, 0.f);
    float4* b4 = reinterpret_cast<float4*>(buf);
    for (long i = t; i < ZERO_N / 4; i += T) b4[i] = z;
    for (long i = t; i < TOTV; i += T) cnt[i] = 0;
    float4* pxa = reinterpret_cast<float4*>(buf + O_PXA);
    for (long v = t; v < NV0; v += T)
        pxa[v] = make_float4(pos[v * 3], pos[v * 3 + 1], pos[v * 3 + 2], x[v]);
}

// ---------------------------------------------------------------------------
// Batched CSR build.
// ---------------------------------------------------------------------------
__global__ void __launch_bounds__(256)
hist5_kernel(Batch5 p, int* __restrict__ cnt) {
    int L = blockIdx.y;
    long n4 = p.E[L] >> 2;
    const int4* dst4 = reinterpret_cast<const int4*>(p.e[L] + p.E[L]);
    int* c = cnt + p.voff[L];
    long T = (long)gridDim.x * blockDim.x;
    long t = (long)blockIdx.x * blockDim.x + threadIdx.x;
    int4 d[4]; bool g[4];
    #pragma unroll
    for (int u = 0; u < 4; u++) {
        long i = t + (long)u * T;
        g[u] = i < n4;
        if (g[u]) d[u] = dst4[i];
    }
    #pragma unroll
    for (int u = 0; u < 4; u++) {
        if (g[u]) {
            atomicAdd(&c[d[u].x], 1);
            atomicAdd(&c[d[u].y], 1);
            atomicAdd(&c[d[u].z], 1);
            atomicAdd(&c[d[u].w], 1);
        }
    }
}

__global__ void scan1_kernel(const int* __restrict__ in, int* __restrict__ out,
                             int* __restrict__ out2, int* __restrict__ bsums, int n) {
    __shared__ int tot[256];
    int tid = threadIdx.x;
    long base = (long)blockIdx.x * 2048 + (long)tid * 8;
    int v[8]; int sum = 0;
    #pragma unroll
    for (int j = 0; j < 8; j++) { v[j] = (base + j < n) ? in[base + j] : 0; sum += v[j]; }
    tot[tid] = sum;
    __syncthreads();
    #pragma unroll
    for (int off = 1; off < 256; off <<= 1) {
        int t = (tid >= off) ? tot[tid - off] : 0;
        __syncthreads();
        tot[tid] += t;
        __syncthreads();
    }
    int run = (tid == 0) ? 0 : tot[tid - 1];
    #pragma unroll
    for (int j = 0; j < 8; j++) {
        if (base + j < n) {
            out[base + j] = run;
            if (out2) out2[base + j] = run;
        }
        run += v[j];
    }
    if (bsums && tid == 255) bsums[blockIdx.x] = tot[255];
}

__global__ void scan_add_kernel(int* __restrict__ out, int* __restrict__ out2,
                                const int* __restrict__ boffs, int n) {
    int add = boffs[blockIdx.x];
    long base = (long)blockIdx.x * 2048 + (long)threadIdx.x * 8;
    #pragma unroll
    for (int j = 0; j < 8; j++)
        if (base + j < n) { out[base + j] += add; out2[base + j] += add; }
}

__global__ void __launch_bounds__(256)
bin5_kernel(Batch5 p, int* __restrict__ cur, int* __restrict__ ebin) {
    int L = blockIdx.y;
    long n4 = p.E[L] >> 2;
    const int4* src4 = reinterpret_cast<const int4*>(p.e[L]);
    const int4* dst4 = reinterpret_cast<const int4*>(p.e[L] + p.E[L]);
    int* cu = cur + p.voff[L];
    long T = (long)gridDim.x * blockDim.x;
    long t = (long)blockIdx.x * blockDim.x + threadIdx.x;
    int4 s[4], d[4]; bool g[4];
    #pragma unroll
    for (int u = 0; u < 4; u++) {
        long i = t + (long)u * T;
        g[u] = i < n4;
        if (g[u]) { s[u] = src4[i]; d[u] = dst4[i]; }
    }
    #pragma unroll
    for (int u = 0; u < 4; u++) {
        if (g[u]) {
            int p0 = atomicAdd(&cu[d[u].x], 1);
            int p1 = atomicAdd(&cu[d[u].y], 1);
            int p2 = atomicAdd(&cu[d[u].z], 1);
            int p3 = atomicAdd(&cu[d[u].w], 1);
            ebin[p0] = s[u].x;
            ebin[p1] = s[u].y;
            ebin[p2] = s[u].z;
            ebin[p3] = s[u].w;
        }
    }
}

// ---------------------------------------------------------------------------
// Basis helper
// ---------------------------------------------------------------------------
__device__ __forceinline__ void basis8(float p0, float p1, float p2, float* b) {
    float q0 = 1.f - p0, q1 = 1.f - p1, q2 = 1.f - p2;
    float b00 = q0 * q1, b01 = p0 * q1, b10 = q0 * p1, b11 = p0 * p1;
    b[0] = b00 * q2; b[1] = b01 * q2; b[2] = b10 * q2; b[3] = b11 * q2;
    b[4] = b00 * p2; b[5] = b01 * p2; b[6] = b10 * p2; b[7] = b11 * p2;
}

// ---------------------------------------------------------------------------
// Layer 1 fused: gather (4-edge pipeline) + 24x16 GEMM + maxpool into fc1.
// ---------------------------------------------------------------------------
__device__ __forceinline__ void s1_accum(float4 sp, float dx, float dy, float dz,
                                         float* G) {
    float p0 = __saturatef((dx - sp.x) * 20.0f + 0.5f);
    float p1 = __saturatef((dy - sp.y) * 20.0f + 0.5f);
    float p2 = __saturatef((dz - sp.z) * 20.0f + 0.5f);
    float b[8]; basis8(p0, p1, p2, b);
    #pragma unroll
    for (int s8 = 0; s8 < 8; s8++) {
        G[s8 * 3 + 0] += b[s8] * sp.w;
        G[s8 * 3 + 1] += b[s8] * sp.x;
        G[s8 * 3 + 2] += b[s8] * sp.y;
    }
}

__global__ void __launch_bounds__(256)
spline1_fused_kernel(const int* __restrict__ rowptr, const int* __restrict__ cnt,
                     const int* __restrict__ ebin,
                     const float4* __restrict__ pxa, const int* __restrict__ batch,
                     const float* __restrict__ Wk, const float* __restrict__ Wr,
                     const float* __restrict__ bias,
                     float* __restrict__ fc1, float* __restrict__ posSum,
                     float* __restrict__ cntPool, int V) {
    __shared__ float sWk[24][16];
    __shared__ float sWr[3][16];
    __shared__ float sb[16];
    int tid = threadIdx.x;
    for (int i = tid; i < 24 * 16; i += 256) sWk[i / 16][i % 16] = Wk[i];
    if (tid < 48) sWr[tid / 16][tid % 16] = Wr[tid];
    if (tid < 16) sb[tid] = bias[tid];
    __syncthreads();
    int v = blockIdx.x * 256 + tid;
    if (v >= V) return;

    float G[24];
    #pragma unroll
    for (int k = 0; k < 24; k++) G[k] = 0.f;

    float4 me = pxa[v];
    float dx = me.x, dy = me.y, dz = me.z;
    int start = rowptr[v];
    int deg = cnt[v];
    int j = 0;
    for (; j + 4 <= deg; j += 4) {
        int s0 = ebin[start + j + 0];
        int s1 = ebin[start + j + 1];
        int s2 = ebin[start + j + 2];
        int s3 = ebin[start + j + 3];
        float4 a0 = pxa[s0];
        float4 a1 = pxa[s1];
        float4 a2 = pxa[s2];
        float4 a3 = pxa[s3];
        s1_accum(a0, dx, dy, dz, G);
        s1_accum(a1, dx, dy, dz, G);
        s1_accum(a2, dx, dy, dz, G);
        s1_accum(a3, dx, dy, dz, G);
    }
    for (; j < deg; j++) {
        float4 a0 = pxa[ebin[start + j]];
        s1_accum(a0, dx, dy, dz, G);
    }

    float acc[16];
    #pragma unroll
    for (int c = 0; c < 16; c++) acc[c] = 0.f;
    #pragma unroll
    for (int k = 0; k < 24; k++) {
        float g = G[k];
        #pragma unroll
        for (int c = 0; c < 16; c++) acc[c] += g * sWk[k][c];
    }
    float inv = 1.f / fmaxf((float)deg, 1.f);

    int b_ = batch[v];
    int ix = min(max((int)floorf(dx * 64.f), 0), 63);
    int iy = min(max((int)floorf(dy * 48.f), 0), 47);
    int it = min(max((int)floorf(dz * 8.f), 0), 7);
    long cl = (((long)b_ * 64 + ix) * 48 + iy) * 8 + it;
    float* fcrow = fc1 + cl * 19;

    #pragma unroll
    for (int c = 0; c < 16; c++) {
        float val = acc[c] * inv + me.w * sWr[0][c] + dx * sWr[1][c]
                  + dy * sWr[2][c] + sb[c];
        val = fmaxf(val, 0.f);
        atomicMax((int*)(fcrow + c), __float_as_int(val));
    }
    atomicAdd(posSum + cl * 3 + 0, dx);
    atomicAdd(posSum + cl * 3 + 1, dy);
    atomicAdd(posSum + cl * 3 + 2, dz);
    atomicAdd(cntPool + cl, 1.0f);
}

// ---------------------------------------------------------------------------
// finalize: row width C+3; writes px,py,pz into row[C..C+2].
// ---------------------------------------------------------------------------
template <int C>
__global__ void finalize_kernel(float* __restrict__ fc, const float* __restrict__ posSum,
                                const float* __restrict__ cnt, int V, int isMean) {
    int v = blockIdx.x * blockDim.x + threadIdx.x;
    if (v >= V) return;
    float cn = fmaxf(cnt[v], 1.0f);
    float inv = 1.0f / cn;
    float px = posSum[(long)v * 3 + 0] * inv;
    float py = posSum[(long)v * 3 + 1] * inv;
    float pz = posSum[(long)v * 3 + 2] * inv;
    float* row = fc + (long)v * (C + 3);
    row[C] = px;
    row[C + 1] = py;
    row[C + 2] = pz;
    if (isMean)
        for (int k = 0; k < C; k++) row[k] *= inv;
}

// ---------------------------------------------------------------------------
// Fully fused layer (2..5): paired-edge pipelined gather into smem rows
// [G(K1) | deg*feat(CIN) | zero-pad], then ONE merged GEMM loop over
// KT = 9*CIN against [Wk; Wr] using packed fma.rn.f32x2, epilogue scales
// by 1/deg, adds bias, relu, pool/out. POOL: 0 none, 1 max, 2 mean.
// ---------------------------------------------------------------------------
template <int CIN, int COUT, int TV, int POOL, bool WOUT>
__global__ void __launch_bounds__(256)
spline_fused_kernel(const int* __restrict__ rowptr, const int* __restrict__ cnt,
                    const int* __restrict__ ebin,
                    const float* __restrict__ featP,  // [V, CIN+1]
                    const float* __restrict__ Wk, const float* __restrict__ Wr,
                    const float* __restrict__ bias,
                    float* __restrict__ out, int V, float inv2mv,
                    int cellsPrev, int nx, int ny, int nt,
                    float* __restrict__ fcN, float* __restrict__ posSum,
                    float* __restrict__ cntPool) {
    constexpr int W = CIN + 1;
    constexpr int K1 = 8 * CIN;
    constexpr int KT = 9 * CIN;             // K1 + CIN
    constexpr int NCH = (KT + 31) / 32;
    constexpr int STR = NCH * 32;           // row stride (zero-padded tail)
    constexpr int NJ = (CIN + 31) / 32;
    constexpr int NPW = TV / 8;
    constexpr int RT = TV / 16;
    constexpr int CT = COUT / 64;

    extern __shared__ float sm[];
    float* Gs = sm;                      // [TV][STR]
    float* Ws = Gs + TV * STR;           // [32][COUT]
    float* sInv = Ws + 32 * COUT;        // [TV]

    int tid = threadIdx.x;
    int lane = tid & 31, warp = tid >> 5;
    int v0 = blockIdx.x * TV;

    // ---- Phase 1: paired-edge pipelined gather ----
    for (int t = 0; t < NPW; t++) {
        int n = warp * NPW + t;
        int v = v0 + n;
        const float* vrow = featP + (long)v * W;
        float dx = vrow[CIN - 2];
        float dy = vrow[CIN - 1];
        float dz = vrow[CIN];
        int start = rowptr[v];
        int deg = cnt[v];
        float Gacc[NJ][8];
        #pragma unroll
        for (int jj = 0; jj < NJ; jj++)
            #pragma unroll
            for (int s8 = 0; s8 < 8; s8++) Gacc[jj][s8] = 0.f;

        int j = 0;
        for (; j + 2 <= deg; j += 2) {
            int sA = ebin[start + j];
            int sB = ebin[start + j + 1];
            const float* rA = featP + (long)sA * W;
            const float* rB = featP + (long)sB * W;
            float fA[NJ], fB[NJ];
            #pragma unroll
            for (int jj = 0; jj < NJ; jj++) {
                int idx = lane + jj * 32;
                fA[jj] = (idx < CIN) ? rA[idx] : 0.f;
                fB[jj] = (idx < CIN) ? rB[idx] : 0.f;
            }
            float axp = rA[CIN - 2], ayp = rA[CIN - 1], azp = rA[CIN];
            float bxp = rB[CIN - 2], byp = rB[CIN - 1], bzp = rB[CIN];
            {
                float p0 = __saturatef((dx - axp) * inv2mv + 0.5f);
                float p1 = __saturatef((dy - ayp) * inv2mv + 0.5f);
                float p2 = __saturatef((dz - azp) * inv2mv + 0.5f);
                float b[8]; basis8(p0, p1, p2, b);
                #pragma unroll
                for (int s8 = 0; s8 < 8; s8++)
                    #pragma unroll
                    for (int jj = 0; jj < NJ; jj++) Gacc[jj][s8] += b[s8] * fA[jj];
            }
            {
                float p0 = __saturatef((dx - bxp) * inv2mv + 0.5f);
                float p1 = __saturatef((dy - byp) * inv2mv + 0.5f);
                float p2 = __saturatef((dz - bzp) * inv2mv + 0.5f);
                float b[8]; basis8(p0, p1, p2, b);
                #pragma unroll
                for (int s8 = 0; s8 < 8; s8++)
                    #pragma unroll
                    for (int jj = 0; jj < NJ; jj++) Gacc[jj][s8] += b[s8] * fB[jj];
            }
        }
        for (; j < deg; j++) {
            int s = ebin[start + j];
            const float* rA = featP + (long)s * W;
            float fA[NJ];
            #pragma unroll
            for (int jj = 0; jj < NJ; jj++) {
                int idx = lane + jj * 32;
                fA[jj] = (idx < CIN) ? rA[idx] : 0.f;
            }
            float p0 = __saturatef((dx - rA[CIN - 2]) * inv2mv + 0.5f);
            float p1 = __saturatef((dy - rA[CIN - 1]) * inv2mv + 0.5f);
            float p2 = __saturatef((dz - rA[CIN]) * inv2mv + 0.5f);
            float b[8]; basis8(p0, p1, p2, b);
            #pragma unroll
            for (int s8 = 0; s8 < 8; s8++)
                #pragma unroll
                for (int jj = 0; jj < NJ; jj++) Gacc[jj][s8] += b[s8] * fA[jj];
        }

        float dS = fmaxf((float)deg, 1.f);
        float* grow = Gs + (long)n * STR;
        #pragma unroll
        for (int s8 = 0; s8 < 8; s8++)
            #pragma unroll
            for (int jj = 0; jj < NJ; jj++) {
                int idx = lane + jj * 32;
                if (idx < CIN) grow[s8 * CIN + idx] = Gacc[jj][s8];
            }
        // deg-scaled feature row at [K1..KT)
        #pragma unroll
        for (int jj = 0; jj < NJ; jj++) {
            int idx = lane + jj * 32;
            if (idx < CIN) grow[K1 + idx] = dS * vrow[idx];
        }
        // zero-pad tail [KT..STR) (STR-KT < 32)
        if (lane < STR - KT) grow[KT + lane] = 0.f;
        if (lane == 0) sInv[n] = 1.f / dS;
    }
    __syncthreads();

    // ---- Phase 2: merged GEMM over KT with packed f32x2 ----
    int tx = tid & 15, ty = tid >> 4;
    u64 acc2[RT][CT][2];
    #pragma unroll
    for (int i = 0; i < RT; i++)
        #pragma unroll
        for (int g = 0; g < CT; g++) { acc2[i][g][0] = 0ull; acc2[i][g][1] = 0ull; }

    for (int k0 = 0; k0 < KT; k0 += 32) {
        // stream weights: rows < K1 from Wk, [K1..KT) from Wr, else 0
        #pragma unroll
        for (int j = 0; j < 32 * COUT / 256; j++) {
            int idx = tid + j * 256;
            int kk = idx / COUT, cc = idx - kk * COUT;
            int k = k0 + kk;
            float w = 0.f;
            if (k < K1) w = Wk[(long)k * COUT + cc];
            else if (k < KT) w = Wr[(long)(k - K1) * COUT + cc];
            Ws[kk * COUT + cc] = w;
        }
        __syncthreads();
        #pragma unroll
        for (int kq = 0; kq < 8; kq++) {
            float4 a[RT];
            #pragma unroll
            for (int i = 0; i < RT; i++)
                a[i] = *(const float4*)&Gs[(long)(ty * RT + i) * STR + k0 + kq * 4];
            ulonglong2 b2[4][CT];
            #pragma unroll
            for (int t = 0; t < 4; t++)
                #pragma unroll
                for (int g = 0; g < CT; g++)
                    b2[t][g] = *(const ulonglong2*)&Ws[(kq * 4 + t) * COUT + g * 64 + tx * 4];
            #pragma unroll
            for (int i = 0; i < RT; i++) {
                u64 a0 = pk2(a[i].x), a1 = pk2(a[i].y);
                u64 a2 = pk2(a[i].z), a3 = pk2(a[i].w);
                #pragma unroll
                for (int g = 0; g < CT; g++) {
                    FMA2(acc2[i][g][0], a0, b2[0][g].x);
                    FMA2(acc2[i][g][1], a0, b2[0][g].y);
                    FMA2(acc2[i][g][0], a1, b2[1][g].x);
                    FMA2(acc2[i][g][1], a1, b2[1][g].y);
                    FMA2(acc2[i][g][0], a2, b2[2][g].x);
                    FMA2(acc2[i][g][1], a2, b2[2][g].y);
                    FMA2(acc2[i][g][0], a3, b2[3][g].x);
                    FMA2(acc2[i][g][1], a3, b2[3][g].y);
                }
            }
        }
        __syncthreads();
    }

    // ---- Epilogue ----
    #pragma unroll
    for (int i = 0; i < RT; i++) {
        int v = v0 + ty * RT + i;
        float inv = sInv[ty * RT + i];
        long cl = 0;
        float px = 0.f, py = 0.f, pz = 0.f;
        if (POOL != 0) {
            const float* vrow = featP + (long)v * W;
            px = vrow[CIN - 2];
            py = vrow[CIN - 1];
            pz = vrow[CIN];
            int b_ = v / cellsPrev;
            int ix = min(max((int)floorf(px * nx), 0), nx - 1);
            int iy = min(max((int)floorf(py * ny), 0), ny - 1);
            int it = min(max((int)floorf(pz * nt), 0), nt - 1);
            cl = (((long)b_ * nx + ix) * ny + iy) * nt + it;
        }
        #pragma unroll
        for (int g = 0; g < CT; g++) {
            int col0 = g * 64 + tx * 4;
            float2 p0 = up2(acc2[i][g][0]);
            float2 p1 = up2(acc2[i][g][1]);
            float vals[4] = {p0.x, p0.y, p1.x, p1.y};
            #pragma unroll
            for (int u = 0; u < 4; u++) {
                int col = col0 + u;
                float val = fmaxf(vals[u] * inv + bias[col], 0.f);
                if (WOUT) out[(long)v * COUT + col] = val;
                if (POOL == 1)
                    atomicMax((int*)(fcN + cl * (COUT + 3) + col), __float_as_int(val));
                else if (POOL == 2)
                    atomicAdd(fcN + cl * (COUT + 3) + col, val);
            }
        }
        if (POOL != 0 && tx == 0) {
            atomicAdd(posSum + cl * 3 + 0, px);
            atomicAdd(posSum + cl * 3 + 1, py);
            atomicAdd(posSum + cl * 3 + 2, pz);
            atomicAdd(cntPool + cl, 1.0f);
        }
    }
}

// smem sizes per instantiation (floats)
__host__ __device__ constexpr long smF(int CIN, int COUT, int TV) {
    int KT = 9 * CIN;
    int STR = ((KT + 31) / 32) * 32;
    return (long)TV * STR + 32L * COUT + TV;
}
constexpr int SM_L2 = (int)(smF(18, 64, 64) * 4);
constexpr int SM_L3 = (int)(smF(66, 128, 32) * 4);
constexpr int SM_L45 = (int)(smF(130, 128, 16) * 4);

// ---------------------------------------------------------------------------
// Launch
// ---------------------------------------------------------------------------
static inline int cdiv(long a, long b) { return (int)((a + b - 1) / b); }

extern "C" void kernel_launch(void* const* d_in, const int* in_sizes, int n_in,
                              void* d_out, int out_size) {
    const float* x    = (const float*)d_in[0];
    const float* pos0 = (const float*)d_in[1];
    const int*   batch = (const int*)d_in[2];
    const int* e0 = (const int*)d_in[3];
    const int* e1 = (const int*)d_in[4];
    const int* e2 = (const int*)d_in[5];
    const int* e3 = (const int*)d_in[6];
    const int* e4 = (const int*)d_in[7];
    const float* W1 = (const float*)d_in[8];
    const float* R1 = (const float*)d_in[9];
    const float* b1 = (const float*)d_in[10];
    const float* W2 = (const float*)d_in[11];
    const float* R2 = (const float*)d_in[12];
    const float* b2 = (const float*)d_in[13];
    const float* W3 = (const float*)d_in[14];
    const float* R3 = (const float*)d_in[15];
    const float* b3 = (const float*)d_in[16];
    const float* W4 = (const float*)d_in[17];
    const float* R4 = (const float*)d_in[18];
    const float* b4 = (const float*)d_in[19];
    const float* W5 = (const float*)d_in[20];
    const float* R5 = (const float*)d_in[21];
    const float* b5 = (const float*)d_in[22];
    float* out = (float*)d_out;

    float* buf;
    cudaGetSymbolAddress((void**)&buf, g_buf);
    int* ip;
    cudaGetSymbolAddress((void**)&ip, g_csr);
    int* cnt = ip + I_CNT;
    int* row = ip + I_ROW;
    int* cur = ip + I_CUR;
    int* ebin = ip + I_EBIN;
    int* bs = ip + I_BS;
    int* bo = ip + I_BO;

    cudaFuncSetAttribute(spline_fused_kernel<18, 64, 64, 1, false>,
                         cudaFuncAttributeMaxDynamicSharedMemorySize, SM_L2);
    cudaFuncSetAttribute(spline_fused_kernel<66, 128, 32, 1, false>,
                         cudaFuncAttributeMaxDynamicSharedMemorySize, SM_L3);
    cudaFuncSetAttribute(spline_fused_kernel<130, 128, 16, 2, true>,
                         cudaFuncAttributeMaxDynamicSharedMemorySize, SM_L45);
    cudaFuncSetAttribute(spline_fused_kernel<130, 128, 16, 0, true>,
                         cudaFuncAttributeMaxDynamicSharedMemorySize, SM_L45);

    Batch5 P;
    P.e[0] = e0; P.e[1] = e1; P.e[2] = e2; P.e[3] = e3; P.e[4] = e4;
    P.E[0] = NE0; P.E[1] = NE1; P.E[2] = NE2; P.E[3] = NE3; P.E[4] = NE4;
    P.voff[0] = VOFF0; P.voff[1] = VOFF1; P.voff[2] = VOFF2;
    P.voff[3] = VOFF3; P.voff[4] = VOFF4;

    init_kernel<<<512, 256>>>(buf, cnt, pos0, x);

    int hg = cdiv(NE0 / 4, 4 * 256);
    hist5_kernel<<<dim3(hg, 5), 256>>>(P, cnt);
    int nb = cdiv(TOTV, 2048);
    scan1_kernel<<<nb, 256>>>(cnt, row, cur, bs, (int)TOTV);
    scan1_kernel<<<1, 256>>>(bs, bo, nullptr, nullptr, nb);
    scan_add_kernel<<<nb, 256>>>(row, cur, bo, (int)TOTV);
    bin5_kernel<<<dim3(hg, 5), 256>>>(P, cur, ebin);

    // ---------------- Layer 1 ----------------
    spline1_fused_kernel<<<cdiv(NV0, 256), 256>>>(row + VOFF0, cnt + VOFF0, ebin,
        (const float4*)(buf + O_PXA), batch, W1, R1, b1,
        buf + O_FC1, buf + O_P1P, buf + O_CNT1, (int)NV0);
    finalize_kernel<16><<<cdiv(NV1, 256), 256>>>(buf + O_FC1, buf + O_P1P,
        buf + O_CNT1, (int)NV1, 0);

    // ---------------- Layer 2 ----------------
    spline_fused_kernel<18, 64, 64, 1, false><<<cdiv(NV1, 64), 256, SM_L2>>>(
        row + VOFF1, cnt + VOFF1, ebin, buf + O_FC1,
        W2, R2, b2, nullptr, (int)NV1, 10.0f,
        64 * 48 * 8, 32, 24, 4, buf + O_FC2, buf + O_P2P, buf + O_CNT2);
    finalize_kernel<64><<<cdiv(NV2, 256), 256>>>(buf + O_FC2, buf + O_P2P,
        buf + O_CNT2, (int)NV2, 0);

    // ---------------- Layer 3 ----------------
    spline_fused_kernel<66, 128, 32, 1, false><<<cdiv(NV2, 32), 256, SM_L3>>>(
        row + VOFF2, cnt + VOFF2, ebin, buf + O_FC2,
        W3, R3, b3, nullptr, (int)NV2, 6.0f,
        32 * 24 * 4, 16, 12, 2, buf + O_FC3, buf + O_P3P, buf + O_CNT3);
    finalize_kernel<128><<<cdiv(NV3, 256), 256>>>(buf + O_FC3, buf + O_P3P,
        buf + O_CNT3, (int)NV3, 0);

    // ---------------- Layer 4 ----------------
    spline_fused_kernel<130, 128, 16, 2, true><<<cdiv(NV3, 16), 256, SM_L45>>>(
        row + VOFF3, cnt + VOFF3, ebin, buf + O_FC3,
        W4, R4, b4, out, (int)NV3, 3.0f,
        16 * 12 * 2, 8, 6, 1, buf + O_FC4, buf + O_P4P, buf + O_CNT4);
    finalize_kernel<128><<<cdiv(NV4, 256), 256>>>(buf + O_FC4, buf + O_P4P,
        buf + O_CNT4, (int)NV4, 1);

    // ---------------- Layer 5 ----------------
    spline_fused_kernel<130, 128, 16, 0, true><<<cdiv(NV4, 16), 256, SM_L45>>>(
        row + VOFF4, cnt + VOFF4, ebin, buf + O_FC4,
        W5, R5, b5, out + NV3 * 128, (int)NV4, 1.5f,
        1, 1, 1, 1, nullptr, nullptr, nullptr);
}